// round 9
// baseline (speedup 1.0000x reference)
#include <cuda_runtime.h>
#include <cuda_bf16.h>

typedef unsigned long long u64;

// ---- packed f32x2 helpers (sm_100a; ptxas never emits FFMA2 from C++) ----
__device__ __forceinline__ u64 pack2_dup(float v) {
    u64 r; asm("mov.b64 %0, {%1, %1};" : "=l"(r) : "f"(v)); return r;
}
__device__ __forceinline__ u64 pack2(float lo, float hi) {
    u64 r; asm("mov.b64 %0, {%1, %2};" : "=l"(r) : "f"(lo), "f"(hi)); return r;
}
__device__ __forceinline__ void fma2(u64 &d, u64 a, u64 b) {
    asm("fma.rn.f32x2 %0, %1, %2, %0;" : "+l"(d) : "l"(a), "l"(b));
}
__device__ __forceinline__ void add2(u64 &d, u64 a) {
    asm("add.rn.f32x2 %0, %0, %1;" : "+l"(d) : "l"(a));
}
__device__ __forceinline__ void unpack2(u64 v, float &lo, float &hi) {
    asm("mov.b64 {%0, %1}, %2;" : "=f"(lo), "=f"(hi) : "l"(v));
}

// ---- problem geometry ----
// x: [4,20,20,40,40,8]  k: [3,3,3,3,8,16]  out: [4,18,18,38,38,16], VALID, stride 1
constexpr int Tt = 20, Zz = 20, Hh = 40, Ww = 40, CI = 8;
constexpr int Bb = 4;
constexpr int OT = 18, OZ = 18, OH = 38, OW = 38, CO = 16;
constexpr int HP = OH / 2, WP = OW / 2;              // 19 x 19 2x2-point tiles
constexpr int NTILE = Bb * OT * OZ * HP * WP;        // 467,856 tiles
// x strides (floats)
constexpr int XS_H = Ww * CI;                        // 320
constexpr int XS_Z = Hh * XS_H;                      // 12,800
constexpr int XS_T = Zz * XS_Z;                      // 256,000
constexpr int XS_B = Tt * XS_T;                      // 5,120,000

// Weight smem layout: [tap(81)][half(2)][ci4(4)][co(16)], half stride padded
// 64 -> 68 floats so odd lanes (half=1) sit +4 banks from even lanes ->
// the two 16B spans per LDS are bank-disjoint -> conflict-free.
constexpr int WHALF = 68;                            // floats per (tap,half)
constexpr int WTAP  = 2 * WHALF;                     // 136 floats per tap
constexpr int NSW   = 81 * WTAP;                     // 11,016 floats = 44.1 KB
constexpr int NWGT  = 81 * CI * CO;                  // 10,368 floats

constexpr int TPB = 128;                             // 4 CTAs/SM -> 16 warps

// Load one x half-row window: blocks 0..3 (w-points), this lane's ci-half.
__device__ __forceinline__ void load_half_row(float (&r)[16], const float* p) {
    #pragma unroll
    for (int b = 0; b < 4; b++) {
        float4 v = *(const float4*)(p + b * 8);
        r[b * 4 + 0] = v.x; r[b * 4 + 1] = v.y;
        r[b * 4 + 2] = v.z; r[b * 4 + 3] = v.w;
    }
}

// FMA body for one (kt,kz,kh) tap-row, this lane's ci-half (4 ci values).
// swt3 already includes this lane's half offset.
__device__ __forceinline__ void tap_half(
    const float* __restrict__ swt3,
    const float (&lo)[16], const float (&hi)[16], u64 (&acc)[4][8])
{
    #pragma unroll
    for (int kw = 0; kw < 3; kw++) {
        const float* swt = swt3 + kw * WTAP;
        #pragma unroll
        for (int c = 0; c < 4; c++) {
            // 16 couts for this (tap, ci): 4 LDS.128, pair-conflict-free.
            const ulonglong2* wq = (const ulonglong2*)(swt + c * CO);
            ulonglong2 q0 = wq[0];
            ulonglong2 q1 = wq[1];
            ulonglong2 q2 = wq[2];
            ulonglong2 q3 = wq[3];
            #pragma unroll
            for (int ph = 0; ph < 2; ph++) {
                const float (&row)[16] = ph ? hi : lo;
                #pragma unroll
                for (int pw = 0; pw < 2; pw++) {
                    const int p = ph * 2 + pw;
                    u64 xx = pack2_dup(row[(kw + pw) * 4 + c]);
                    fma2(acc[p][0], xx, q0.x);
                    fma2(acc[p][1], xx, q0.y);
                    fma2(acc[p][2], xx, q1.x);
                    fma2(acc[p][3], xx, q1.y);
                    fma2(acc[p][4], xx, q2.x);
                    fma2(acc[p][5], xx, q2.y);
                    fma2(acc[p][6], xx, q3.x);
                    fma2(acc[p][7], xx, q3.y);
                }
            }
        }
    }
}

__global__ void __launch_bounds__(TPB, 4) conv4d_kernel(
    const float* __restrict__ x, const float* __restrict__ wgt,
    const float* __restrict__ bias, float* __restrict__ out)
{
    // Transform weights gmem [tap][ci][co] -> smem [tap][half][ci4][co] padded.
    __shared__ __align__(16) float sw[NSW];
    {
        const float4* g4 = (const float4*)wgt;
        for (int i = threadIdx.x; i < NWGT / 4; i += TPB) {
            int tap = i >> 5;            // /32 float4s per tap
            int r   = i & 31;
            int ci  = r >> 2;            // 0..7
            int c4  = r & 3;             // co quad
            float4 v = g4[i];
            *(float4*)(sw + tap * WTAP + (ci >> 2) * WHALF
                       + (ci & 3) * CO + c4 * 4) = v;
        }
    }
    __syncthreads();

    const int g = blockIdx.x * TPB + threadIdx.x;
    int tile = g >> 1;
    const int half = g & 1;
    const bool active = (tile < NTILE) && (half == 0);
    if (tile >= NTILE) tile = NTILE - 1;   // clamp; pair stays consistent
    int id = tile;
    int wp = id % WP; id /= WP;
    int hp = id % HP; id /= HP;
    int z  = id % OZ; id /= OZ;
    int t  = id % OT;
    int b  = id / OT;
    const int h0 = hp * 2, w0 = wp * 2;

    // This lane's x base: tile origin + ci-half offset.
    const float* xb = x + b * XS_B + t * XS_T + z * XS_Z + h0 * XS_H
                        + w0 * CI + half * 4;
    float* ob = out + (((((b * OT + t) * OZ + z) * OH + h0) * OW + w0) * CO);

    // 4 points x 16 couts partial accs (this ci-half). Bias seeded in half 0.
    u64 acc[4][8];
    #pragma unroll
    for (int cp = 0; cp < 8; cp++) {
        u64 bv = half ? 0ull : pack2(bias[cp * 2], bias[cp * 2 + 1]);
        #pragma unroll
        for (int p = 0; p < 4; p++) acc[p][cp] = bv;
    }

    const float* swh = sw + half * WHALF;

    #pragma unroll 1
    for (int kt = 0; kt < 3; kt++) {
        #pragma unroll 1
        for (int kz = 0; kz < 3; kz++) {
            const float* xp  = xb + kt * XS_T + kz * XS_Z;
            const float* swb = swh + ((kt * 3 + kz) * 3) * 3 * WTAP;
            constexpr int TS = 3 * WTAP;   // per-kh weight stride

            // Rolling 2-row half buffers over kh: 4 unique rows, 4 loads.
            float ra[16], rb[16];
            load_half_row(ra, xp);                     // row h0
            load_half_row(rb, xp + XS_H);              // row h0+1
            tap_half(swb + 0 * TS, ra, rb, acc);       // kh=0
            load_half_row(ra, xp + 2 * XS_H);          // row h0+2
            tap_half(swb + 1 * TS, rb, ra, acc);       // kh=1
            load_half_row(rb, xp + 3 * XS_H);          // row h0+3
            tap_half(swb + 2 * TS, ra, rb, acc);       // kh=2
        }
    }

    // Merge ci-halves: odd lane's partials into even lane.
    #pragma unroll
    for (int p = 0; p < 4; p++)
        #pragma unroll
        for (int cp = 0; cp < 8; cp++) {
            u64 other = __shfl_down_sync(0xFFFFFFFFu, acc[p][cp], 1);
            add2(acc[p][cp], other);
        }

    if (active) {
        #pragma unroll
        for (int ph = 0; ph < 2; ph++)
            #pragma unroll
            for (int pw = 0; pw < 2; pw++) {
                const int p = ph * 2 + pw;
                float* o = ob + (ph * OW + pw) * CO;
                #pragma unroll
                for (int cp = 0; cp < 8; cp += 2) {
                    float4 v;
                    unpack2(acc[p][cp],     v.x, v.y);
                    unpack2(acc[p][cp + 1], v.z, v.w);
                    *(float4*)(o + cp * 2) = v;
                }
            }
    }
}

extern "C" void kernel_launch(void* const* d_in, const int* in_sizes, int n_in,
                              void* d_out, int out_size)
{
    const float* x    = (const float*)d_in[0];
    const float* wgt  = (const float*)d_in[1];
    const float* bias = (const float*)d_in[2];
    float* out        = (float*)d_out;
    const long long nthreads = 2LL * NTILE;
    const int blocks = (int)((nthreads + TPB - 1) / TPB);
    conv4d_kernel<<<blocks, TPB>>>(x, wgt, bias, out);
}

// round 12
// speedup vs baseline: 2.6075x; 2.6075x over previous
#include <cuda_runtime.h>
#include <cuda_fp16.h>
#include <cstdint>

// ---- problem geometry ----
// x: [4,20,20,40,40,8]  k: [3,3,3,3,8,16]  out: [4,18,18,38,38,16]
constexpr int OT = 18, OZ = 18, OH = 38, OW = 38, CO = 16;
constexpr int XS_Z = 12800, XS_T = 256000, XS_B = 5120000;   // x strides (floats)
constexpr int TILES_PP = 12;                 // ceil(38*40/128) point-tiles per plane
constexpr int NBLK = 4 * OT * OZ * TILES_PP; // 15552
constexpr int TPB = 128;

// A staging: plane floats [r0*8, r0*8+1680) as f16. Fragment read for
// (m, kh, k) is halves [(m+kh*40)*8 + k, +1] -- no kh duplication needed.
// Max half index: (127+80)*8+23 = 1679. Gmem float4 clamp: plane has 3200
// float4s; last valid index 3199 (garbage rows feed masked outputs only).
constexpr int NAH = 1696;                    // staged halves (1680 used)
// B: [n(16)][k(88 pitch)] halves; k_total = kh*24 + kw*8 + ci in 0..71.
// Pitch 88 halves = 176 B -> n-lane bank stride 12, disjoint with k lanes.
constexpr int BKP = 88;

__device__ __forceinline__ void mma_f16(
    float& d0, float& d1, float& d2, float& d3,
    uint32_t a0, uint32_t a1, uint32_t b0)
{
    asm volatile(
        "mma.sync.aligned.m16n8k8.row.col.f32.f16.f16.f32 "
        "{%0,%1,%2,%3}, {%4,%5}, {%6}, {%0,%1,%2,%3};"
        : "+f"(d0), "+f"(d1), "+f"(d2), "+f"(d3)
        : "r"(a0), "r"(a1), "r"(b0));
}

__global__ void __launch_bounds__(TPB) conv4d_hmma(
    const float* __restrict__ x, const float* __restrict__ wgt,
    const float* __restrict__ bias, float* __restrict__ out)
{
    __shared__ __align__(16) __half sA[NAH];
    __shared__ __align__(16) __half sB[16 * BKP];

    const int tid  = threadIdx.x;
    const int wrp  = tid >> 5;
    const int lane = tid & 31;
    const int gid  = lane >> 2;      // group-of-4 id (row selector)
    const int tg   = lane & 3;       // thread-in-group (k/col selector)

    int bid = blockIdx.x;
    const int tp = bid % TILES_PP;
    int plane = bid / TILES_PP;
    const int z = plane % OZ; plane /= OZ;
    const int t = plane % OT;
    const int b = plane / OT;
    const int r0 = tp * 128;

    // Per-warp: mtiles {2w, 2w+1} -> rows 32w..32w+31. Accs [mtl][nt][4].
    float acc[2][2][4];
    #pragma unroll
    for (int i = 0; i < 2; i++)
        #pragma unroll
        for (int j = 0; j < 2; j++)
            #pragma unroll
            for (int q = 0; q < 4; q++) acc[i][j][q] = 0.0f;

    const float* xb = x + b * XS_B + t * XS_T + z * XS_Z;

    #pragma unroll 1
    for (int g = 0; g < 9; g++) {
        const int kt = g / 3, kz = g % 3;
        __syncthreads();   // previous group's fragment reads complete

        // ---- stage A: 420 float4 -> 1680 f16 halves ----
        const float4* xpl = (const float4*)(xb + kt * XS_T + kz * XS_Z);
        const int base4 = r0 * 2;
        #pragma unroll
        for (int it = 0; it < 4; it++) {
            int i = tid + it * TPB;
            if (i < 420) {
                int s = base4 + i; if (s > 3199) s = 3199;
                float4 v = xpl[s];
                ((__half2*)sA)[i * 2]     = __floats2half2_rn(v.x, v.y);
                ((__half2*)sA)[i * 2 + 1] = __floats2half2_rn(v.z, v.w);
            }
        }
        // ---- stage B: [kh][kw][ci][co] -> [n][k], k = i>>4, n = i&15 ----
        const float* wg_ = wgt + g * 1152;
        #pragma unroll
        for (int it = 0; it < 9; it++) {
            int i = tid + it * TPB;     // 1152 = 9*128 exactly
            sB[(i & 15) * BKP + (i >> 4)] = __float2half_rn(wg_[i]);
        }
        __syncthreads();

        // ---- compute: 9 k-steps of 8 (3 kh x 3 ks) ----
        const int mrow = 32 * wrp + gid;
        #pragma unroll
        for (int kh = 0; kh < 3; kh++) {
            #pragma unroll
            for (int ks = 0; ks < 3; ks++) {
                const int kf = ks * 8 + tg * 2;          // within 24-window
                const int ab = (mrow + kh * 40) * 8 + kf;
                const int bb = kh * 24 + kf;
                uint32_t a0  = *(const uint32_t*)&sA[ab];            // m
                uint32_t a1  = *(const uint32_t*)&sA[ab + 64];       // m+8
                uint32_t a0b = *(const uint32_t*)&sA[ab + 128];      // m+16
                uint32_t a1b = *(const uint32_t*)&sA[ab + 192];      // m+24
                uint32_t b0  = *(const uint32_t*)&sB[(gid)     * BKP + bb];
                uint32_t b1  = *(const uint32_t*)&sB[(gid + 8) * BKP + bb];
                mma_f16(acc[0][0][0], acc[0][0][1], acc[0][0][2], acc[0][0][3],
                        a0,  a1,  b0);
                mma_f16(acc[0][1][0], acc[0][1][1], acc[0][1][2], acc[0][1][3],
                        a0,  a1,  b1);
                mma_f16(acc[1][0][0], acc[1][0][1], acc[1][0][2], acc[1][0][3],
                        a0b, a1b, b0);
                mma_f16(acc[1][1][0], acc[1][1][1], acc[1][1][2], acc[1][1][3],
                        a0b, a1b, b1);
            }
        }
    }

    // ---- epilogue: D rows 32w + mtl*16 + gid (+8), cols nt*8 + tg*2 (+1) ----
    float* ob = out + ((((long long)b * OT + t) * OZ + z) * (OH * OW)) * CO;
    #pragma unroll
    for (int mtl = 0; mtl < 2; mtl++) {
        #pragma unroll
        for (int half = 0; half < 2; half++) {     // row / row+8 (c0c1 vs c2c3)
            const int m = 32 * wrp + mtl * 16 + gid + half * 8;
            const int p = r0 + m;
            const int h = p / 40, w_ = p - h * 40;
            if (h < OH && w_ < OW) {
                float* o = ob + (h * OW + w_) * CO;
                #pragma unroll
                for (int nt = 0; nt < 2; nt++) {
                    const int n0 = nt * 8 + tg * 2;
                    float2 v;
                    v.x = acc[mtl][nt][half * 2 + 0] + bias[n0];
                    v.y = acc[mtl][nt][half * 2 + 1] + bias[n0 + 1];
                    *(float2*)(o + n0) = v;
                }
            }
        }
    }
}

extern "C" void kernel_launch(void* const* d_in, const int* in_sizes, int n_in,
                              void* d_out, int out_size)
{
    const float* x    = (const float*)d_in[0];
    const float* wgt  = (const float*)d_in[1];
    const float* bias = (const float*)d_in[2];
    float* out        = (float*)d_out;
    conv4d_hmma<<<NBLK, TPB>>>(x, wgt, bias, out);
}

// round 13
// speedup vs baseline: 3.2646x; 1.2520x over previous
#include <cuda_runtime.h>
#include <cuda_fp16.h>
#include <cstdint>

// ---- problem geometry ----
// x: [4,20,20,40,40,8]  k: [3,3,3,3,8,16]  out: [4,18,18,38,38,16]
constexpr int OT = 18, OZ = 18, OH = 38, OW = 38, CO = 16;
constexpr int XS_Z = 12800, XS_T = 256000, XS_B = 5120000;   // x strides (floats)
constexpr int TILE_M = 256;                  // points per CTA (64 per warp)
constexpr int TILES_PP = 6;                  // ceil(38*40/256)
constexpr int NBLK = 4 * OT * OZ * TILES_PP; // 7776
constexpr int TPB = 128;

// A staging: halves [r0*8, r0*8 + 2704) of the plane (338 rows); fragment
// read for (m, kh, k) is halves [(m+kh*40)*8 + k]. Valid points p<1520 use
// rows <= 1599 (all in-plane); slab overreach rows are clamped & masked.
constexpr int NAH = 2704;
// B: [g(9)][n(16)][k(88 pitch)] halves; k_total = kh*24 + kw*8 + ci (0..71).
constexpr int BKP = 88;
constexpr int BGS = 16 * BKP;                // halves per group

__device__ __forceinline__ void mma_f16(
    float& d0, float& d1, float& d2, float& d3,
    uint32_t a0, uint32_t a1, uint32_t b0)
{
    asm volatile(
        "mma.sync.aligned.m16n8k8.row.col.f32.f16.f16.f32 "
        "{%0,%1,%2,%3}, {%4,%5}, {%6}, {%0,%1,%2,%3};"
        : "+f"(d0), "+f"(d1), "+f"(d2), "+f"(d3)
        : "r"(a0), "r"(a1), "r"(b0));
}

__global__ void __launch_bounds__(TPB) conv4d_hmma(
    const float* __restrict__ x, const float* __restrict__ wgt,
    const float* __restrict__ bias, float* __restrict__ out)
{
    __shared__ __align__(16) __half sA[NAH];
    __shared__ __align__(16) __half sB[9 * BGS];

    const int tid  = threadIdx.x;
    const int wrp  = tid >> 5;
    const int lane = tid & 31;
    const int gid  = lane >> 2;      // group-of-4 id (row selector)
    const int tg   = lane & 3;       // thread-in-group (k/col selector)

    int bid = blockIdx.x;
    const int tp = bid % TILES_PP;
    int plane = bid / TILES_PP;
    const int z = plane % OZ; plane /= OZ;
    const int t = plane % OT;
    const int b = plane / OT;
    const int r0 = tp * TILE_M;

    // ---- stage ALL 9 weight groups once: [kh][kw][ci][co] -> [g][n][k] ----
    {
        #pragma unroll
        for (int it = 0; it < 81; it++) {       // 10368 = 81*128 exactly
            int i = tid + it * TPB;
            int g = i / 1152, r = i - g * 1152;
            sB[g * BGS + (r & 15) * BKP + (r >> 4)] = __float2half_rn(wgt[i]);
        }
    }

    // Per-warp: 2 row-halves (ms) x 2 mtiles x 2 ntiles x 4 accs = 32 f32.
    float acc[2][2][2][4];
    #pragma unroll
    for (int s = 0; s < 2; s++)
        #pragma unroll
        for (int i = 0; i < 2; i++)
            #pragma unroll
            for (int j = 0; j < 2; j++)
                #pragma unroll
                for (int q = 0; q < 4; q++) acc[s][i][j][q] = 0.0f;

    const float* xb = x + b * XS_B + t * XS_T + z * XS_Z;

    #pragma unroll 1
    for (int g = 0; g < 9; g++) {
        const int kt = g / 3, kz = g % 3;
        __syncthreads();   // previous group's sA reads complete (also covers sB stage at g=0)

        // ---- stage A: 676 float4 -> 2704 f16 halves ----
        const float4* xpl = (const float4*)(xb + kt * XS_T + kz * XS_Z);
        const int base4 = r0 * 2;
        #pragma unroll
        for (int it = 0; it < 6; it++) {
            int i = tid + it * TPB;
            if (i < 676) {
                int s = base4 + i; if (s > 3199) s = 3199;
                float4 v = xpl[s];
                ((__half2*)sA)[i * 2]     = __floats2half2_rn(v.x, v.y);
                ((__half2*)sA)[i * 2 + 1] = __floats2half2_rn(v.z, v.w);
            }
        }
        __syncthreads();

        // ---- compute: 9 k8-steps (3 kh x 3 ks), B-frags shared across ms ----
        const __half* sBg = sB + g * BGS;
        #pragma unroll
        for (int kh = 0; kh < 3; kh++) {
            #pragma unroll
            for (int ks = 0; ks < 3; ks++) {
                const int kf = ks * 8 + tg * 2;          // within 24-window
                const int bb = kh * 24 + kf;
                uint32_t b0 = *(const uint32_t*)&sBg[(gid)     * BKP + bb];
                uint32_t b1 = *(const uint32_t*)&sBg[(gid + 8) * BKP + bb];
                #pragma unroll
                for (int ms = 0; ms < 2; ms++) {
                    const int mrow = 64 * wrp + ms * 32 + gid;
                    const int ab = (mrow + kh * 40) * 8 + kf;
                    uint32_t a0  = *(const uint32_t*)&sA[ab];            // m
                    uint32_t a1  = *(const uint32_t*)&sA[ab + 64];       // m+8
                    uint32_t a0b = *(const uint32_t*)&sA[ab + 128];      // m+16
                    uint32_t a1b = *(const uint32_t*)&sA[ab + 192];      // m+24
                    mma_f16(acc[ms][0][0][0], acc[ms][0][0][1],
                            acc[ms][0][0][2], acc[ms][0][0][3], a0,  a1,  b0);
                    mma_f16(acc[ms][0][1][0], acc[ms][0][1][1],
                            acc[ms][0][1][2], acc[ms][0][1][3], a0,  a1,  b1);
                    mma_f16(acc[ms][1][0][0], acc[ms][1][0][1],
                            acc[ms][1][0][2], acc[ms][1][0][3], a0b, a1b, b0);
                    mma_f16(acc[ms][1][1][0], acc[ms][1][1][1],
                            acc[ms][1][1][2], acc[ms][1][1][3], a0b, a1b, b1);
                }
            }
        }
    }

    // ---- epilogue ----
    float* ob = out + ((((long long)b * OT + t) * OZ + z) * (OH * OW)) * CO;
    #pragma unroll
    for (int ms = 0; ms < 2; ms++) {
        #pragma unroll
        for (int mtl = 0; mtl < 2; mtl++) {
            #pragma unroll
            for (int half = 0; half < 2; half++) {   // row / row+8
                const int m = 64 * wrp + ms * 32 + mtl * 16 + gid + half * 8;
                const int p = r0 + m;
                const int h = p / 40, w_ = p - h * 40;
                if (h < OH && w_ < OW) {
                    float* o = ob + (h * OW + w_) * CO;
                    #pragma unroll
                    for (int nt = 0; nt < 2; nt++) {
                        const int n0 = nt * 8 + tg * 2;
                        float2 v;
                        v.x = acc[ms][mtl][nt][half * 2 + 0] + bias[n0];
                        v.y = acc[ms][mtl][nt][half * 2 + 1] + bias[n0 + 1];
                        *(float2*)(o + n0) = v;
                    }
                }
            }
        }
    }
}

extern "C" void kernel_launch(void* const* d_in, const int* in_sizes, int n_in,
                              void* d_out, int out_size)
{
    const float* x    = (const float*)d_in[0];
    const float* wgt  = (const float*)d_in[1];
    const float* bias = (const float*)d_in[2];
    float* out        = (float*)d_out;
    conv4d_hmma<<<NBLK, TPB>>>(x, wgt, bias, out);
}

// round 15
// speedup vs baseline: 3.2956x; 1.0095x over previous
#include <cuda_runtime.h>
#include <cuda_fp16.h>
#include <cstdint>

// ---- problem geometry ----
// x: [4,20,20,40,40,8]  k: [3,3,3,3,8,16]  out: [4,18,18,38,38,16]
constexpr int OT = 18, OZ = 18, OH = 38, OW = 38, CO = 16;
constexpr int XS_Z = 12800, XS_T = 256000, XS_B = 5120000;   // x strides (floats)
constexpr int TILE_M = 256;                  // points per CTA (64 per warp)
constexpr int TILES_PP = 6;                  // ceil(38*40/256)
constexpr int NBLK = 4 * OT * OZ * TILES_PP; // 7776
constexpr int TPB = 128;

// A staging: halves [r0*8, r0*8 + 2704) of the plane (338 rows); fragment
// read for (m, kh, k) is halves [(m+kh*40)*8 + k]. Valid points p<1520 use
// rows <= 1599 (in-plane); slab overreach rows are clamped & masked.
constexpr int NAH = 2704;
constexpr int NPF = 6;                       // float4 prefetch slots (676 total)
// B: [g(9)][n(16)][k(88 pitch)] halves; k_total = kh*24 + kw*8 + ci (0..71).
constexpr int BKP = 88;
constexpr int BGS = 16 * BKP;                // halves per group

__device__ __forceinline__ void mma_f16(
    float& d0, float& d1, float& d2, float& d3,
    uint32_t a0, uint32_t a1, uint32_t b0)
{
    asm volatile(
        "mma.sync.aligned.m16n8k8.row.col.f32.f16.f16.f32 "
        "{%0,%1,%2,%3}, {%4,%5}, {%6}, {%0,%1,%2,%3};"
        : "+f"(d0), "+f"(d1), "+f"(d2), "+f"(d3)
        : "r"(a0), "r"(a1), "r"(b0));
}

__global__ void __launch_bounds__(TPB) conv4d_hmma(
    const float* __restrict__ x, const float* __restrict__ wgt,
    const float* __restrict__ bias, float* __restrict__ out)
{
    __shared__ __align__(16) __half sA[2][NAH];
    __shared__ __align__(16) __half sB[9 * BGS];

    const int tid  = threadIdx.x;
    const int wrp  = tid >> 5;
    const int lane = tid & 31;
    const int gid  = lane >> 2;      // group-of-4 id (row selector)
    const int tg   = lane & 3;       // thread-in-group (k/col selector)

    int bid = blockIdx.x;
    const int tp = bid % TILES_PP;
    int plane = bid / TILES_PP;
    const int z = plane % OZ; plane /= OZ;
    const int t = plane % OT;
    const int b = plane / OT;
    const int r0 = tp * TILE_M;

    // ---- stage ALL 9 weight groups once: [kh][kw][ci][co] -> [g][n][k] ----
    #pragma unroll
    for (int it = 0; it < 81; it++) {           // 10368 = 81*128 exactly
        int i = tid + it * TPB;
        int g = i / 1152, r = i - g * 1152;
        sB[g * BGS + (r & 15) * BKP + (r >> 4)] = __float2half_rn(wgt[i]);
    }

    float acc[2][2][2][4];
    #pragma unroll
    for (int s = 0; s < 2; s++)
        #pragma unroll
        for (int i = 0; i < 2; i++)
            #pragma unroll
            for (int j = 0; j < 2; j++)
                #pragma unroll
                for (int q = 0; q < 4; q++) acc[s][i][j][q] = 0.0f;

    const float* xb = x + b * XS_B + t * XS_T + z * XS_Z;
    const int base4 = r0 * 2;

    // Prefetch group 0's A plane chunk into registers.
    float4 pf[NPF];
    {
        const float4* xpl = (const float4*)xb;   // kt=0, kz=0
        #pragma unroll
        for (int it = 0; it < NPF; it++) {
            int i = tid + it * TPB;
            if (i < 676) {
                int s = base4 + i; if (s > 3199) s = 3199;
                pf[it] = xpl[s];
            }
        }
    }

    #pragma unroll 1
    for (int g = 0; g < 9; g++) {
        const int buf = g & 1;

        // ---- convert + STS prefetched A into sA[buf] ----
        #pragma unroll
        for (int it = 0; it < NPF; it++) {
            int i = tid + it * TPB;
            if (i < 676) {
                ((__half2*)sA[buf])[i * 2]     = __floats2half2_rn(pf[it].x, pf[it].y);
                ((__half2*)sA[buf])[i * 2 + 1] = __floats2half2_rn(pf[it].z, pf[it].w);
            }
        }
        __syncthreads();     // sA[buf] ready; also fences prior buf readers & sB@g=0

        // ---- prefetch group g+1 (LDG latency hides behind compute) ----
        if (g < 8) {
            const int gn = g + 1;
            const float4* xpl =
                (const float4*)(xb + (gn / 3) * XS_T + (gn % 3) * XS_Z);
            #pragma unroll
            for (int it = 0; it < NPF; it++) {
                int i = tid + it * TPB;
                if (i < 676) {
                    int s = base4 + i; if (s > 3199) s = 3199;
                    pf[it] = xpl[s];
                }
            }
        }

        // ---- compute: 9 k8-steps (3 kh x 3 ks), B-frags shared across ms ----
        const __half* sAb = sA[buf];
        const __half* sBg = sB + g * BGS;
        #pragma unroll
        for (int kh = 0; kh < 3; kh++) {
            #pragma unroll
            for (int ks = 0; ks < 3; ks++) {
                const int kf = ks * 8 + tg * 2;          // within 24-window
                const int bb = kh * 24 + kf;
                uint32_t b0 = *(const uint32_t*)&sBg[(gid)     * BKP + bb];
                uint32_t b1 = *(const uint32_t*)&sBg[(gid + 8) * BKP + bb];
                #pragma unroll
                for (int ms = 0; ms < 2; ms++) {
                    const int mrow = 64 * wrp + ms * 32 + gid;
                    const int ab = (mrow + kh * 40) * 8 + kf;
                    uint32_t a0  = *(const uint32_t*)&sAb[ab];            // m
                    uint32_t a1  = *(const uint32_t*)&sAb[ab + 64];       // m+8
                    uint32_t a0b = *(const uint32_t*)&sAb[ab + 128];      // m+16
                    uint32_t a1b = *(const uint32_t*)&sAb[ab + 192];      // m+24
                    mma_f16(acc[ms][0][0][0], acc[ms][0][0][1],
                            acc[ms][0][0][2], acc[ms][0][0][3], a0,  a1,  b0);
                    mma_f16(acc[ms][0][1][0], acc[ms][0][1][1],
                            acc[ms][0][1][2], acc[ms][0][1][3], a0,  a1,  b1);
                    mma_f16(acc[ms][1][0][0], acc[ms][1][0][1],
                            acc[ms][1][0][2], acc[ms][1][0][3], a0b, a1b, b0);
                    mma_f16(acc[ms][1][1][0], acc[ms][1][1][1],
                            acc[ms][1][1][2], acc[ms][1][1][3], a0b, a1b, b1);
                }
            }
        }
    }

    // ---- epilogue ----
    float* ob = out + ((((long long)b * OT + t) * OZ + z) * (OH * OW)) * CO;
    #pragma unroll
    for (int ms = 0; ms < 2; ms++) {
        #pragma unroll
        for (int mtl = 0; mtl < 2; mtl++) {
            #pragma unroll
            for (int half = 0; half < 2; half++) {   // row / row+8
                const int m = 64 * wrp + ms * 32 + mtl * 16 + gid + half * 8;
                const int p = r0 + m;
                const int h = p / 40, w_ = p - h * 40;
                if (h < OH && w_ < OW) {
                    float* o = ob + (h * OW + w_) * CO;
                    #pragma unroll
                    for (int nt = 0; nt < 2; nt++) {
                        const int n0 = nt * 8 + tg * 2;
                        float2 v;
                        v.x = acc[ms][mtl][nt][half * 2 + 0] + bias[n0];
                        v.y = acc[ms][mtl][nt][half * 2 + 1] + bias[n0 + 1];
                        *(float2*)(o + n0) = v;
                    }
                }
            }
        }
    }
}

extern "C" void kernel_launch(void* const* d_in, const int* in_sizes, int n_in,
                              void* d_out, int out_size)
{
    const float* x    = (const float*)d_in[0];
    const float* wgt  = (const float*)d_in[1];
    const float* bias = (const float*)d_in[2];
    float* out        = (float*)d_out;
    conv4d_hmma<<<NBLK, TPB>>>(x, wgt, bias, out);
}

// round 16
// speedup vs baseline: 3.7609x; 1.1412x over previous
#include <cuda_runtime.h>
#include <cuda_fp16.h>
#include <cstdint>

// ---- problem geometry ----
// x: [4,20,20,40,40,8]  k: [3,3,3,3,8,16]  out: [4,18,18,38,38,16]
constexpr int OT = 18, OZ = 18, OH = 38, OW = 38, CO = 16;
constexpr int XS_Z = 12800, XS_T = 256000, XS_B = 5120000;   // x strides (floats)
constexpr int TILE_M = 256;                  // points per CTA (64 per warp)
constexpr int TILES_PP = 6;                  // ceil(38*40/256)
constexpr int NBLK = 4 * OT * OZ * TILES_PP; // 7776
constexpr int TPB = 128;

// A staging: halves [r0*8, r0*8 + 2704) of the plane (338 rows); fragment
// read for (m, kh, k) is halves [(m+kh*40)*8 + k]. Valid points p<1520 use
// rows <= 1599 (in-plane); slab overreach rows are clamped & masked.
constexpr int NAH = 2704;
constexpr int NPF = 6;                       // float4 prefetch slots (676 total)
// B: [g(9)][n(16)][k(88 pitch)] halves; k_total = kh*24 + kw*8 + ci (0..71).
constexpr int BKP = 88;
constexpr int BGS = 16 * BKP;                // halves per group

__device__ __forceinline__ void mma_k8(
    float* d, uint32_t a0, uint32_t a1, uint32_t b0)
{
    asm volatile(
        "mma.sync.aligned.m16n8k8.row.col.f32.f16.f16.f32 "
        "{%0,%1,%2,%3}, {%4,%5}, {%6}, {%0,%1,%2,%3};"
        : "+f"(d[0]), "+f"(d[1]), "+f"(d[2]), "+f"(d[3])
        : "r"(a0), "r"(a1), "r"(b0));
}
__device__ __forceinline__ void mma_k16(
    float* d, uint32_t a0, uint32_t a1, uint32_t a2, uint32_t a3,
    uint32_t b0, uint32_t b1)
{
    asm volatile(
        "mma.sync.aligned.m16n8k16.row.col.f32.f16.f16.f32 "
        "{%0,%1,%2,%3}, {%4,%5,%6,%7}, {%8,%9}, {%0,%1,%2,%3};"
        : "+f"(d[0]), "+f"(d[1]), "+f"(d[2]), "+f"(d[3])
        : "r"(a0), "r"(a1), "r"(a2), "r"(a3), "r"(b0), "r"(b1));
}

__global__ void __launch_bounds__(TPB) conv4d_hmma(
    const float* __restrict__ x, const float* __restrict__ wgt,
    const float* __restrict__ bias, float* __restrict__ out)
{
    __shared__ __align__(16) __half sA[2][NAH];
    __shared__ __align__(16) __half sB[9 * BGS];

    const int tid  = threadIdx.x;
    const int wrp  = tid >> 5;
    const int lane = tid & 31;
    const int gid  = lane >> 2;      // group-of-4 id (row selector)
    const int tg   = lane & 3;       // thread-in-group (k/col selector)

    int bid = blockIdx.x;
    const int tp = bid % TILES_PP;
    int plane = bid / TILES_PP;
    const int z = plane % OZ; plane /= OZ;
    const int t = plane % OT;
    const int b = plane / OT;
    const int r0 = tp * TILE_M;

    // ---- stage ALL 9 weight groups once: [kh][kw][ci][co] -> [g][n][k] ----
    #pragma unroll
    for (int it = 0; it < 81; it++) {           // 10368 = 81*128 exactly
        int i = tid + it * TPB;
        int g = i / 1152, r = i - g * 1152;
        sB[g * BGS + (r & 15) * BKP + (r >> 4)] = __float2half_rn(wgt[i]);
    }

    float acc[2][2][2][4];
    #pragma unroll
    for (int s = 0; s < 2; s++)
        #pragma unroll
        for (int i = 0; i < 2; i++)
            #pragma unroll
            for (int j = 0; j < 2; j++)
                #pragma unroll
                for (int q = 0; q < 4; q++) acc[s][i][j][q] = 0.0f;

    const float* xb = x + b * XS_B + t * XS_T + z * XS_Z;
    const int base4 = r0 * 2;

    // Prefetch group 0's A plane chunk into registers.
    float4 pf[NPF];
    {
        const float4* xpl = (const float4*)xb;   // kt=0, kz=0
        #pragma unroll
        for (int it = 0; it < NPF; it++) {
            int i = tid + it * TPB;
            if (i < 676) {
                int s = base4 + i; if (s > 3199) s = 3199;
                pf[it] = xpl[s];
            }
        }
    }

    #pragma unroll 1
    for (int g = 0; g < 9; g++) {
        const int buf = g & 1;

        // ---- convert + STS prefetched A into sA[buf] ----
        #pragma unroll
        for (int it = 0; it < NPF; it++) {
            int i = tid + it * TPB;
            if (i < 676) {
                ((__half2*)sA[buf])[i * 2]     = __floats2half2_rn(pf[it].x, pf[it].y);
                ((__half2*)sA[buf])[i * 2 + 1] = __floats2half2_rn(pf[it].z, pf[it].w);
            }
        }
        __syncthreads();     // sA[buf] ready; also fences prior buf readers & sB@g=0

        // ---- prefetch group g+1 (LDG latency hides behind compute) ----
        if (g < 8) {
            const int gn = g + 1;
            const float4* xpl =
                (const float4*)(xb + (gn / 3) * XS_T + (gn % 3) * XS_Z);
            #pragma unroll
            for (int it = 0; it < NPF; it++) {
                int i = tid + it * TPB;
                if (i < 676) {
                    int s = base4 + i; if (s > 3199) s = 3199;
                    pf[it] = xpl[s];
                }
            }
        }

        // ---- compute: pair the 9 k8 windows -> 4 x k16 + 1 x k8 ----
        // window w (0..8): kh = w/3, ks = w%3; A base (m) = (m+kh*40)*8+ks*8,
        // B base = kh*24+ks*8. Pairing across kh is fine: k16 fragments are
        // two independent k8 chunks (a2/a3, b1 carry the second chunk).
        const __half* sAb = sA[buf];
        const __half* sBg = sB + g * BGS;
        const int kf = tg * 2;
        #pragma unroll
        for (int pr = 0; pr < 4; pr++) {
            const int w0 = pr * 2, w1 = w0 + 1;
            const int kh0 = w0 / 3, ks0 = w0 % 3;
            const int kh1 = w1 / 3, ks1 = w1 % 3;
            const int bb0 = kh0 * 24 + ks0 * 8 + kf;
            const int bb1 = kh1 * 24 + ks1 * 8 + kf;
            uint32_t b0 = *(const uint32_t*)&sBg[(gid)     * BKP + bb0];
            uint32_t b1 = *(const uint32_t*)&sBg[(gid)     * BKP + bb1];
            uint32_t c0 = *(const uint32_t*)&sBg[(gid + 8) * BKP + bb0];
            uint32_t c1 = *(const uint32_t*)&sBg[(gid + 8) * BKP + bb1];
            #pragma unroll
            for (int ms = 0; ms < 2; ms++) {
                const int mrow = 64 * wrp + ms * 32 + gid;
                const int ab0 = (mrow + kh0 * 40) * 8 + ks0 * 8 + kf;
                const int ab1 = (mrow + kh1 * 40) * 8 + ks1 * 8 + kf;
                uint32_t a0  = *(const uint32_t*)&sAb[ab0];
                uint32_t a1  = *(const uint32_t*)&sAb[ab0 + 64];
                uint32_t a2  = *(const uint32_t*)&sAb[ab1];
                uint32_t a3  = *(const uint32_t*)&sAb[ab1 + 64];
                uint32_t a0b = *(const uint32_t*)&sAb[ab0 + 128];
                uint32_t a1b = *(const uint32_t*)&sAb[ab0 + 192];
                uint32_t a2b = *(const uint32_t*)&sAb[ab1 + 128];
                uint32_t a3b = *(const uint32_t*)&sAb[ab1 + 192];
                mma_k16(acc[ms][0][0], a0,  a1,  a2,  a3,  b0, b1);
                mma_k16(acc[ms][0][1], a0,  a1,  a2,  a3,  c0, c1);
                mma_k16(acc[ms][1][0], a0b, a1b, a2b, a3b, b0, b1);
                mma_k16(acc[ms][1][1], a0b, a1b, a2b, a3b, c0, c1);
            }
        }
        {   // leftover window 8: kh=2, ks=2 (k8)
            const int bb = 2 * 24 + 2 * 8 + kf;
            uint32_t b0 = *(const uint32_t*)&sBg[(gid)     * BKP + bb];
            uint32_t c0 = *(const uint32_t*)&sBg[(gid + 8) * BKP + bb];
            #pragma unroll
            for (int ms = 0; ms < 2; ms++) {
                const int mrow = 64 * wrp + ms * 32 + gid;
                const int ab = (mrow + 2 * 40) * 8 + 2 * 8 + kf;
                uint32_t a0  = *(const uint32_t*)&sAb[ab];
                uint32_t a1  = *(const uint32_t*)&sAb[ab + 64];
                uint32_t a0b = *(const uint32_t*)&sAb[ab + 128];
                uint32_t a1b = *(const uint32_t*)&sAb[ab + 192];
                mma_k8(acc[ms][0][0], a0,  a1,  b0);
                mma_k8(acc[ms][0][1], a0,  a1,  c0);
                mma_k8(acc[ms][1][0], a0b, a1b, b0);
                mma_k8(acc[ms][1][1], a0b, a1b, c0);
            }
        }
    }

    // ---- epilogue ----
    float* ob = out + ((((long long)b * OT + t) * OZ + z) * (OH * OW)) * CO;
    #pragma unroll
    for (int ms = 0; ms < 2; ms++) {
        #pragma unroll
        for (int mtl = 0; mtl < 2; mtl++) {
            #pragma unroll
            for (int half = 0; half < 2; half++) {   // row / row+8
                const int m = 64 * wrp + ms * 32 + mtl * 16 + gid + half * 8;
                const int p = r0 + m;
                const int h = p / 40, w_ = p - h * 40;
                if (h < OH && w_ < OW) {
                    float* o = ob + (h * OW + w_) * CO;
                    #pragma unroll
                    for (int nt = 0; nt < 2; nt++) {
                        const int n0 = nt * 8 + tg * 2;
                        float2 v;
                        v.x = acc[ms][mtl][nt][half * 2 + 0] + bias[n0];
                        v.y = acc[ms][mtl][nt][half * 2 + 1] + bias[n0 + 1];
                        *(float2*)(o + n0) = v;
                    }
                }
            }
        }
    }
}

extern "C" void kernel_launch(void* const* d_in, const int* in_sizes, int n_in,
                              void* d_out, int out_size)
{
    const float* x    = (const float*)d_in[0];
    const float* wgt  = (const float*)d_in[1];
    const float* bias = (const float*)d_in[2];
    float* out        = (float*)d_out;
    conv4d_hmma<<<NBLK, TPB>>>(x, wgt, bias, out);
}